// round 3
// baseline (speedup 1.0000x reference)
#include <cuda_runtime.h>
#include <cstdint>

#define NODE_EMB 128
#define EDGE_EMB 16
#define D_IN     160      // 128 + 2*16
#define N_MAX    100000

#define TILE_N   64
#define THREADS  512
#define SC_THREADS 256

// Scratch: scatter-mean accumulators (device globals — no cudaMalloc allowed)
__device__ float g_rec [N_MAX * EDGE_EMB];
__device__ float g_sent[N_MAX * EDGE_EMB];
__device__ float g_rcnt[N_MAX];
__device__ float g_scnt[N_MAX];

// ---------------- packed f32x2 helpers (sm_100+) ----------------
__device__ __forceinline__ unsigned long long pack2(float lo, float hi) {
    unsigned long long r;
    asm("mov.b64 %0, {%1, %2};" : "=l"(r) : "f"(lo), "f"(hi));
    return r;
}
__device__ __forceinline__ unsigned long long bcast2(float v) {
    unsigned long long r;
    asm("mov.b64 %0, {%1, %1};" : "=l"(r) : "f"(v));
    return r;
}
__device__ __forceinline__ void fma2(unsigned long long& d,
                                     unsigned long long a,
                                     unsigned long long b) {
    asm("fma.rn.f32x2 %0, %1, %2, %0;" : "+l"(d) : "l"(a), "l"(b));
}
__device__ __forceinline__ void unpack2(unsigned long long v, float& lo, float& hi) {
    asm("mov.b64 {%0, %1}, %2;" : "=f"(lo), "=f"(hi) : "l"(v));
}

// ---------------- kernel 1: zero accumulators ----------------
__global__ void zero_kernel(int N) {
    int stride = gridDim.x * blockDim.x;
    int t = blockIdx.x * blockDim.x + threadIdx.x;
    int total4 = N * EDGE_EMB / 4;
    float4 z = make_float4(0.f, 0.f, 0.f, 0.f);
    for (int i = t; i < total4; i += stride) {
        reinterpret_cast<float4*>(g_rec)[i]  = z;
        reinterpret_cast<float4*>(g_sent)[i] = z;
    }
    for (int i = t; i < N; i += stride) {
        g_rcnt[i] = 0.f;
        g_scnt[i] = 0.f;
    }
}

// ---------------- kernel 2: fused dual scatter-sum via 64B bulk reduce ----------------
// One thread per edge: stage the 64B edge_attr row in smem once, then issue TWO
// cp.reduce.async.bulk (one per direction) from the same staging buffer.
// 2 bulk requests/edge replaces 8x red.v4 requests/edge.
__global__ __launch_bounds__(SC_THREADS)
void scatter_kernel(const float4* __restrict__ edge_attr4,
                    const int* __restrict__ edge_index,
                    int E) {
    __shared__ __align__(128) float stage[SC_THREADS * EDGE_EMB];  // 64B per thread
    int e = blockIdx.x * SC_THREADS + threadIdx.x;
    if (e >= E) return;

    // Stage this edge's 16 floats into smem
    float4* my = reinterpret_cast<float4*>(&stage[threadIdx.x * EDGE_EMB]);
    #pragma unroll
    for (int j = 0; j < 4; ++j)
        my[j] = edge_attr4[(size_t)e * 4 + j];

    int row = edge_index[e];        // receiver
    int col = edge_index[E + e];    // sender

    // Make generic-proxy smem writes visible to the async proxy
    asm volatile("fence.proxy.async.shared::cta;" ::: "memory");

    uint32_t src;
    asm("{ .reg .u64 t; cvta.to.shared.u64 t, %1; cvt.u32.u64 %0, t; }"
        : "=r"(src) : "l"((const void*)my));

    float* pr = &g_rec [row * EDGE_EMB];
    float* ps = &g_sent[col * EDGE_EMB];
    asm volatile(
        "cp.reduce.async.bulk.global.shared::cta.bulk_group.add.f32 [%0], [%1], 64;"
        :: "l"(pr), "r"(src) : "memory");
    asm volatile(
        "cp.reduce.async.bulk.global.shared::cta.bulk_group.add.f32 [%0], [%1], 64;"
        :: "l"(ps), "r"(src) : "memory");

    // Degree counts (scalar no-return reductions)
    atomicAdd(&g_rcnt[row], 1.0f);
    atomicAdd(&g_scnt[col], 1.0f);

    asm volatile("cp.async.bulk.commit_group;" ::: "memory");
    asm volatile("cp.async.bulk.wait_group 0;" ::: "memory");
}

// ---------------- kernel 3: fused concat + MLP (unchanged from R2) ----------------
__global__ __launch_bounds__(THREADS, 1)
void mlp_kernel(const float* __restrict__ x,
                const float* __restrict__ W1,
                const float* __restrict__ b1,
                const float* __restrict__ W2,
                const float* __restrict__ b2,
                float* __restrict__ out,
                int N) {
    extern __shared__ unsigned long long smem_u64[];
    unsigned long long* Ad = smem_u64;                          // 64*160 ull
    float* W1s = reinterpret_cast<float*>(Ad + TILE_N * D_IN);  // 160*128 f
    float* W2s = W1s + D_IN * NODE_EMB;                         // 128*128 f

    int tid = threadIdx.x;
    int tx = tid & 31;
    int ty = tid >> 5;
    int node0 = blockIdx.x * TILE_N;

    for (int i = tid; i < (D_IN * NODE_EMB) / 4; i += THREADS)
        reinterpret_cast<float4*>(W1s)[i] = reinterpret_cast<const float4*>(W1)[i];
    for (int i = tid; i < (NODE_EMB * NODE_EMB) / 4; i += THREADS)
        reinterpret_cast<float4*>(W2s)[i] = reinterpret_cast<const float4*>(W2)[i];

    for (int idx = tid; idx < TILE_N * D_IN; idx += THREADS) {
        int nl = idx / D_IN;
        int k  = idx - nl * D_IN;
        int n  = node0 + nl;
        float v = 0.f;
        if (n < N) {
            if (k < NODE_EMB) {
                v = x[(size_t)n * NODE_EMB + k];
            } else if (k < NODE_EMB + EDGE_EMB) {
                float c = g_rcnt[n];
                v = g_rec[n * EDGE_EMB + (k - NODE_EMB)] / fmaxf(c, 1.f);
            } else {
                float c = g_scnt[n];
                v = g_sent[n * EDGE_EMB + (k - NODE_EMB - EDGE_EMB)] / fmaxf(c, 1.f);
            }
        }
        Ad[idx] = bcast2(v);
    }
    __syncthreads();

    unsigned long long acc[4][2];
    {
        float4 bv = *reinterpret_cast<const float4*>(&b1[tx * 4]);
        unsigned long long b01 = pack2(bv.x, bv.y);
        unsigned long long b23 = pack2(bv.z, bv.w);
        #pragma unroll
        for (int i = 0; i < 4; ++i) { acc[i][0] = b01; acc[i][1] = b23; }
    }
    #pragma unroll 8
    for (int k = 0; k < D_IN; ++k) {
        ulonglong2 w = *reinterpret_cast<const ulonglong2*>(&W1s[k * NODE_EMB + tx * 4]);
        #pragma unroll
        for (int i = 0; i < 4; ++i) {
            unsigned long long a2 = Ad[(ty * 4 + i) * D_IN + k];
            fma2(acc[i][0], a2, w.x);
            fma2(acc[i][1], a2, w.y);
        }
    }
    __syncthreads();

    #pragma unroll
    for (int i = 0; i < 4; ++i) {
        float h0, h1, h2, h3;
        unpack2(acc[i][0], h0, h1);
        unpack2(acc[i][1], h2, h3);
        h0 = (h0 >= 0.f) ? h0 : 0.01f * h0;
        h1 = (h1 >= 0.f) ? h1 : 0.01f * h1;
        h2 = (h2 >= 0.f) ? h2 : 0.01f * h2;
        h3 = (h3 >= 0.f) ? h3 : 0.01f * h3;
        unsigned long long* hr = &Ad[(ty * 4 + i) * NODE_EMB + tx * 4];
        hr[0] = bcast2(h0);
        hr[1] = bcast2(h1);
        hr[2] = bcast2(h2);
        hr[3] = bcast2(h3);
    }
    __syncthreads();

    {
        float4 bv = *reinterpret_cast<const float4*>(&b2[tx * 4]);
        unsigned long long b01 = pack2(bv.x, bv.y);
        unsigned long long b23 = pack2(bv.z, bv.w);
        #pragma unroll
        for (int i = 0; i < 4; ++i) { acc[i][0] = b01; acc[i][1] = b23; }
    }
    #pragma unroll 8
    for (int k = 0; k < NODE_EMB; ++k) {
        ulonglong2 w = *reinterpret_cast<const ulonglong2*>(&W2s[k * NODE_EMB + tx * 4]);
        #pragma unroll
        for (int i = 0; i < 4; ++i) {
            unsigned long long a2 = Ad[(ty * 4 + i) * NODE_EMB + k];
            fma2(acc[i][0], a2, w.x);
            fma2(acc[i][1], a2, w.y);
        }
    }

    #pragma unroll
    for (int i = 0; i < 4; ++i) {
        int n = node0 + ty * 4 + i;
        if (n < N) {
            float o0, o1, o2, o3;
            unpack2(acc[i][0], o0, o1);
            unpack2(acc[i][1], o2, o3);
            float4 ov = make_float4(o0, o1, o2, o3);
            *reinterpret_cast<float4*>(&out[(size_t)n * NODE_EMB + tx * 4]) = ov;
        }
    }
}

// ---------------- launch ----------------
extern "C" void kernel_launch(void* const* d_in, const int* in_sizes, int n_in,
                              void* d_out, int out_size) {
    const float* x          = (const float*)d_in[0];
    const int*   edge_index = (const int*)  d_in[1];
    const float* edge_attr  = (const float*)d_in[2];
    const float* W1         = (const float*)d_in[3];
    const float* b1         = (const float*)d_in[4];
    const float* W2         = (const float*)d_in[5];
    const float* b2         = (const float*)d_in[6];
    float* out = (float*)d_out;

    int N = in_sizes[0] / NODE_EMB;
    int E = in_sizes[2] / EDGE_EMB;

    zero_kernel<<<1184, 256>>>(N);

    scatter_kernel<<<(E + SC_THREADS - 1) / SC_THREADS, SC_THREADS>>>(
        reinterpret_cast<const float4*>(edge_attr), edge_index, E);

    const int smem_bytes = (TILE_N * D_IN * 2 + D_IN * NODE_EMB + NODE_EMB * NODE_EMB) * 4; // 229376
    cudaFuncSetAttribute(mlp_kernel, cudaFuncAttributeMaxDynamicSharedMemorySize, smem_bytes);
    mlp_kernel<<<(N + TILE_N - 1) / TILE_N, THREADS, smem_bytes>>>(
        x, W1, b1, W2, b2, out, N);
}

// round 4
// speedup vs baseline: 1.1933x; 1.1933x over previous
#include <cuda_runtime.h>
#include <cstdint>

#define NODE_EMB 128
#define EDGE_EMB 16
#define D_IN     160      // 128 + 2*16
#define N_MAX    100000

#define TILE_N   128
#define THREADS  512
#define AS_STRIDE 132     // 128 nodes + pad: 16B-aligned rows (132*4=528=33*16), bank step 4
#define SC_THREADS 256

// Scratch: scatter-mean accumulators (device globals — no cudaMalloc allowed)
__device__ float g_rec [N_MAX * EDGE_EMB];
__device__ float g_sent[N_MAX * EDGE_EMB];
__device__ float g_rcnt[N_MAX];
__device__ float g_scnt[N_MAX];

// ---------------- packed f32x2 helpers (sm_100+) ----------------
__device__ __forceinline__ unsigned long long pack2(float lo, float hi) {
    unsigned long long r;
    asm("mov.b64 %0, {%1, %2};" : "=l"(r) : "f"(lo), "f"(hi));
    return r;
}
__device__ __forceinline__ unsigned long long bcast2(float v) {
    unsigned long long r;
    asm("mov.b64 %0, {%1, %1};" : "=l"(r) : "f"(v));
    return r;
}
__device__ __forceinline__ void fma2(unsigned long long& d,
                                     unsigned long long a,
                                     unsigned long long b) {
    asm("fma.rn.f32x2 %0, %1, %2, %0;" : "+l"(d) : "l"(a), "l"(b));
}
__device__ __forceinline__ void unpack2(unsigned long long v, float& lo, float& hi) {
    asm("mov.b64 {%0, %1}, %2;" : "=f"(lo), "=f"(hi) : "l"(v));
}

// ---------------- kernel 1: zero accumulators ----------------
__global__ void zero_kernel(int N) {
    int stride = gridDim.x * blockDim.x;
    int t = blockIdx.x * blockDim.x + threadIdx.x;
    int total4 = N * EDGE_EMB / 4;
    float4 z = make_float4(0.f, 0.f, 0.f, 0.f);
    for (int i = t; i < total4; i += stride) {
        reinterpret_cast<float4*>(g_rec)[i]  = z;
        reinterpret_cast<float4*>(g_sent)[i] = z;
    }
    for (int i = t; i < N; i += stride) {
        g_rcnt[i] = 0.f;
        g_scnt[i] = 0.f;
    }
}

// ---------------- kernel 2: fused dual scatter-sum via 64B bulk reduce ----------------
// (unchanged from R3 — control; L2 f32-ALU-bound, ~240us)
__global__ __launch_bounds__(SC_THREADS)
void scatter_kernel(const float4* __restrict__ edge_attr4,
                    const int* __restrict__ edge_index,
                    int E) {
    __shared__ __align__(128) float stage[SC_THREADS * EDGE_EMB];
    int e = blockIdx.x * SC_THREADS + threadIdx.x;
    if (e >= E) return;

    float4* my = reinterpret_cast<float4*>(&stage[threadIdx.x * EDGE_EMB]);
    #pragma unroll
    for (int j = 0; j < 4; ++j)
        my[j] = edge_attr4[(size_t)e * 4 + j];

    int row = edge_index[e];
    int col = edge_index[E + e];

    asm volatile("fence.proxy.async.shared::cta;" ::: "memory");

    uint32_t src;
    asm("{ .reg .u64 t; cvta.to.shared.u64 t, %1; cvt.u32.u64 %0, t; }"
        : "=r"(src) : "l"((const void*)my));

    float* pr = &g_rec [row * EDGE_EMB];
    float* ps = &g_sent[col * EDGE_EMB];
    asm volatile(
        "cp.reduce.async.bulk.global.shared::cta.bulk_group.add.f32 [%0], [%1], 64;"
        :: "l"(pr), "r"(src) : "memory");
    asm volatile(
        "cp.reduce.async.bulk.global.shared::cta.bulk_group.add.f32 [%0], [%1], 64;"
        :: "l"(ps), "r"(src) : "memory");

    atomicAdd(&g_rcnt[row], 1.0f);
    atomicAdd(&g_scnt[col], 1.0f);

    asm volatile("cp.async.bulk.commit_group;" ::: "memory");
    asm volatile("cp.async.bulk.wait_group 0;" ::: "memory");
}

// ---------------- kernel 3: fused concat + MLP (v3: transposed-A node-pair scheme) ----------------
// 512 threads, TILE_N=128. Thread (ty=warp, tx=lane): 8 nodes (4 f32x2 node-pairs)
// x 4 cols (strided: tx, tx+32, tx+64, tx+96).
// A^T stored [k][node] (stride 132). Inner loop per k:
//   2x LDS.128 broadcast (A node-pairs, 2 wf) + 4x LDS.32 (W cols, 4 wf)
//   + 4 dup-movs + 16 FFMA2  ->  LDS 96 wf/SM/k < FMA 128 cyc/SM/k  => fma-bound.
// SMEM: A^T 160x132 (84480B, reused as h^T 128x132) + W1 81920B + W2 65536B = 231936B.
__global__ __launch_bounds__(THREADS, 1)
void mlp_kernel(const float* __restrict__ x,
                const float* __restrict__ W1,
                const float* __restrict__ b1,
                const float* __restrict__ W2,
                const float* __restrict__ b2,
                float* __restrict__ out,
                int N) {
    extern __shared__ float smem_f[];
    float* As  = smem_f;                        // [D_IN][AS_STRIDE] transposed A / h
    float* W1s = As + D_IN * AS_STRIDE;         // [160][128]
    float* W2s = W1s + D_IN * NODE_EMB;         // [128][128]

    int tid = threadIdx.x;
    int tx = tid & 31;
    int ty = tid >> 5;
    int node0 = blockIdx.x * TILE_N;

    // Cooperative weight loads
    for (int i = tid; i < (D_IN * NODE_EMB) / 4; i += THREADS)
        reinterpret_cast<float4*>(W1s)[i] = reinterpret_cast<const float4*>(W1)[i];
    for (int i = tid; i < (NODE_EMB * NODE_EMB) / 4; i += THREADS)
        reinterpret_cast<float4*>(W2s)[i] = reinterpret_cast<const float4*>(W2)[i];

    // Stage A^T: concat(x, rec_mean, sent_mean), transposed [k][node]
    for (int idx = tid; idx < TILE_N * D_IN; idx += THREADS) {
        int nl = idx / D_IN;
        int k  = idx - nl * D_IN;
        int n  = node0 + nl;
        float v = 0.f;
        if (n < N) {
            if (k < NODE_EMB) {
                v = x[(size_t)n * NODE_EMB + k];
            } else if (k < NODE_EMB + EDGE_EMB) {
                float c = g_rcnt[n];
                v = g_rec[n * EDGE_EMB + (k - NODE_EMB)] / fmaxf(c, 1.f);
            } else {
                float c = g_scnt[n];
                v = g_sent[n * EDGE_EMB + (k - NODE_EMB - EDGE_EMB)] / fmaxf(c, 1.f);
            }
        }
        As[k * AS_STRIDE + nl] = v;
    }
    __syncthreads();

    // ---- Phase 1: h = A @ W1 + b1 ----
    unsigned long long acc[4][4];   // [node-pair j][col cc]
    #pragma unroll
    for (int cc = 0; cc < 4; ++cc) {
        unsigned long long bb = bcast2(b1[tx + 32 * cc]);
        #pragma unroll
        for (int j = 0; j < 4; ++j) acc[j][cc] = bb;
    }
    #pragma unroll 4
    for (int k = 0; k < D_IN; ++k) {
        const float* ar = &As[k * AS_STRIDE + ty * 8];
        ulonglong2 a01 = *reinterpret_cast<const ulonglong2*>(ar);      // nodes 0-3 (bcast)
        ulonglong2 a23 = *reinterpret_cast<const ulonglong2*>(ar + 4);  // nodes 4-7 (bcast)
        const float* wr = &W1s[k * NODE_EMB + tx];
        #pragma unroll
        for (int cc = 0; cc < 4; ++cc) {
            unsigned long long wd = bcast2(wr[32 * cc]);
            fma2(acc[0][cc], a01.x, wd);
            fma2(acc[1][cc], a01.y, wd);
            fma2(acc[2][cc], a23.x, wd);
            fma2(acc[3][cc], a23.y, wd);
        }
    }
    __syncthreads();   // all reads of As done before overwrite

    // LeakyReLU + store h^T[c][node] (STS.64 node-pairs, cols strided => 4-way)
    #pragma unroll
    for (int cc = 0; cc < 4; ++cc) {
        int c = tx + 32 * cc;
        #pragma unroll
        for (int j = 0; j < 4; ++j) {
            float v0, v1;
            unpack2(acc[j][cc], v0, v1);
            v0 = (v0 >= 0.f) ? v0 : 0.01f * v0;
            v1 = (v1 >= 0.f) ? v1 : 0.01f * v1;
            *reinterpret_cast<unsigned long long*>(&As[c * AS_STRIDE + ty * 8 + 2 * j])
                = pack2(v0, v1);
        }
    }
    __syncthreads();

    // ---- Phase 2: out = h @ W2 + b2 ----
    #pragma unroll
    for (int cc = 0; cc < 4; ++cc) {
        unsigned long long bb = bcast2(b2[tx + 32 * cc]);
        #pragma unroll
        for (int j = 0; j < 4; ++j) acc[j][cc] = bb;
    }
    #pragma unroll 4
    for (int k = 0; k < NODE_EMB; ++k) {
        const float* ar = &As[k * AS_STRIDE + ty * 8];
        ulonglong2 a01 = *reinterpret_cast<const ulonglong2*>(ar);
        ulonglong2 a23 = *reinterpret_cast<const ulonglong2*>(ar + 4);
        const float* wr = &W2s[k * NODE_EMB + tx];
        #pragma unroll
        for (int cc = 0; cc < 4; ++cc) {
            unsigned long long wd = bcast2(wr[32 * cc]);
            fma2(acc[0][cc], a01.x, wd);
            fma2(acc[1][cc], a01.y, wd);
            fma2(acc[2][cc], a23.x, wd);
            fma2(acc[3][cc], a23.y, wd);
        }
    }

    // Store out[n][c] (coalesced across tx per (node, cc) group)
    #pragma unroll
    for (int j = 0; j < 4; ++j) {
        int n0i = node0 + ty * 8 + 2 * j;
        #pragma unroll
        for (int cc = 0; cc < 4; ++cc) {
            float v0, v1;
            unpack2(acc[j][cc], v0, v1);
            int c = tx + 32 * cc;
            if (n0i < N)     out[(size_t)n0i * NODE_EMB + c]       = v0;
            if (n0i + 1 < N) out[(size_t)(n0i + 1) * NODE_EMB + c] = v1;
        }
    }
}

// ---------------- launch ----------------
extern "C" void kernel_launch(void* const* d_in, const int* in_sizes, int n_in,
                              void* d_out, int out_size) {
    const float* x          = (const float*)d_in[0];
    const int*   edge_index = (const int*)  d_in[1];
    const float* edge_attr  = (const float*)d_in[2];
    const float* W1         = (const float*)d_in[3];
    const float* b1         = (const float*)d_in[4];
    const float* W2         = (const float*)d_in[5];
    const float* b2         = (const float*)d_in[6];
    float* out = (float*)d_out;

    int N = in_sizes[0] / NODE_EMB;
    int E = in_sizes[2] / EDGE_EMB;

    zero_kernel<<<1184, 256>>>(N);

    scatter_kernel<<<(E + SC_THREADS - 1) / SC_THREADS, SC_THREADS>>>(
        reinterpret_cast<const float4*>(edge_attr), edge_index, E);

    const int smem_bytes = (D_IN * AS_STRIDE + D_IN * NODE_EMB + NODE_EMB * NODE_EMB) * 4; // 231936
    cudaFuncSetAttribute(mlp_kernel, cudaFuncAttributeMaxDynamicSharedMemorySize, smem_bytes);
    mlp_kernel<<<(N + TILE_N - 1) / TILE_N, THREADS, smem_bytes>>>(
        x, W1, b1, W2, b2, out, N);
}